// round 2
// baseline (speedup 1.0000x reference)
#include <cuda_runtime.h>
#include <cstdint>

#define N_NODES 100000
#define D 256

// Scratch for side = A @ ego (102.4 MB). Device global per allocation rules.
__device__ float g_side[(size_t)N_NODES * D];

// ---------------------------------------------------------------------------
// Kernel 1: zero the side buffer (float4 stores, grid exactly covers buffer)
// ---------------------------------------------------------------------------
__global__ void zero_side_kernel() {
    size_t i = (size_t)blockIdx.x * blockDim.x + threadIdx.x;
    float4 z = make_float4(0.f, 0.f, 0.f, 0.f);
    reinterpret_cast<float4*>(g_side)[i] = z;
}

// ---------------------------------------------------------------------------
// Kernel 2: COO SpMM scatter. One warp per edge; each lane handles 2 float4
// (8 floats) of the 256-wide row. Accumulate with red.global.add.v4.f32
// (vectorized, no-return reduction) to minimize atomic instruction count.
// ---------------------------------------------------------------------------
__global__ void spmm_scatter_kernel(const float* __restrict__ ego,
                                    const float* __restrict__ vals,
                                    const int*   __restrict__ rows,
                                    const int*   __restrict__ cols,
                                    int E) {
    int w = (int)(((size_t)blockIdx.x * blockDim.x + threadIdx.x) >> 5);
    if (w >= E) return;
    int lane = threadIdx.x & 31;

    int   r = __ldg(rows + w);
    int   c = __ldg(cols + w);
    float v = __ldg(vals + w);

    const float4* src = reinterpret_cast<const float4*>(ego) + (size_t)c * (D / 4);
    float4*       dst = reinterpret_cast<float4*>(g_side)    + (size_t)r * (D / 4);

#pragma unroll
    for (int i = 0; i < 2; i++) {
        float4 x = __ldg(src + lane + 32 * i);
        float4* p = dst + lane + 32 * i;
        asm volatile("red.global.add.v4.f32 [%0], {%1, %2, %3, %4};"
                     :: "l"(p), "f"(x.x * v), "f"(x.y * v),
                        "f"(x.z * v), "f"(x.w * v)
                     : "memory");
    }
}

// ---------------------------------------------------------------------------
// Kernel 3: fused dual GEMM + epilogue.
//   a1 = ego + side ; a2 = ego * side          (computed at smem-load time)
//   out = lrelu(a1 @ W1^T + b1) + lrelu(a2 @ W2^T + b2)
// Tiling: BM=64, BN=64, BK=16; 256 threads; 4x4 microtile per thread,
// two accumulator sets (one per GEMM path). Smem tiles stored K-major with
// +4 padding so float4 LDS stays 16B-aligned and conflict-free.
// ---------------------------------------------------------------------------
#define BM 64
#define BN 64
#define BK 16
#define PADM (BM + 4)

__device__ __forceinline__ float lrelu(float x) {
    return x > 0.f ? x : 0.01f * x;
}

__global__ __launch_bounds__(256) void fused_gemm_kernel(
    const float* __restrict__ ego,
    const float* __restrict__ W1, const float* __restrict__ b1,
    const float* __restrict__ W2, const float* __restrict__ b2,
    float* __restrict__ out) {

    __shared__ float sA1[BK][PADM];
    __shared__ float sA2[BK][PADM];
    __shared__ float sW1[BK][PADM];
    __shared__ float sW2[BK][PADM];

    int t  = threadIdx.x;
    int i0 = blockIdx.x * BM;   // row tile origin
    int j0 = blockIdx.y * BN;   // col tile origin

    // loader mapping: 256 threads cover 64 rows x 16 k (one float4 of k each)
    int lr = t >> 2;            // 0..63 : tile row
    int lk = (t & 3) * 4;       // 0,4,8,12 : k-quad start

    // compute mapping: 16x16 thread grid, each 4x4 outputs
    int ty = t >> 4;            // 0..15
    int tx = t & 15;            // 0..15

    float acc1[4][4] = {};
    float acc2[4][4] = {};

    for (int k0 = 0; k0 < D; k0 += BK) {
        // ---- load A tiles (ego & side fused into a1/a2) ----
        int gi = i0 + lr;
        float4 e, s;
        if (gi < N_NODES) {
            e = *reinterpret_cast<const float4*>(ego    + (size_t)gi * D + k0 + lk);
            s = *reinterpret_cast<const float4*>(g_side + (size_t)gi * D + k0 + lk);
        } else {
            e = make_float4(0.f, 0.f, 0.f, 0.f);
            s = e;
        }
        sA1[lk + 0][lr] = e.x + s.x;  sA2[lk + 0][lr] = e.x * s.x;
        sA1[lk + 1][lr] = e.y + s.y;  sA2[lk + 1][lr] = e.y * s.y;
        sA1[lk + 2][lr] = e.z + s.z;  sA2[lk + 2][lr] = e.z * s.z;
        sA1[lk + 3][lr] = e.w + s.w;  sA2[lk + 3][lr] = e.w * s.w;

        // ---- load W tiles (j0+lr always < 256) ----
        float4 w1 = *reinterpret_cast<const float4*>(W1 + (size_t)(j0 + lr) * D + k0 + lk);
        float4 w2 = *reinterpret_cast<const float4*>(W2 + (size_t)(j0 + lr) * D + k0 + lk);
        sW1[lk + 0][lr] = w1.x;  sW2[lk + 0][lr] = w2.x;
        sW1[lk + 1][lr] = w1.y;  sW2[lk + 1][lr] = w2.y;
        sW1[lk + 2][lr] = w1.z;  sW2[lk + 2][lr] = w2.z;
        sW1[lk + 3][lr] = w1.w;  sW2[lk + 3][lr] = w2.w;

        __syncthreads();

#pragma unroll
        for (int k = 0; k < BK; k++) {
            float4 a1 = *reinterpret_cast<float4*>(&sA1[k][ty * 4]);
            float4 a2 = *reinterpret_cast<float4*>(&sA2[k][ty * 4]);
            float4 v1 = *reinterpret_cast<float4*>(&sW1[k][tx * 4]);
            float4 v2 = *reinterpret_cast<float4*>(&sW2[k][tx * 4]);
            float av1[4] = {a1.x, a1.y, a1.z, a1.w};
            float av2[4] = {a2.x, a2.y, a2.z, a2.w};
            float wv1[4] = {v1.x, v1.y, v1.z, v1.w};
            float wv2[4] = {v2.x, v2.y, v2.z, v2.w};
#pragma unroll
            for (int i = 0; i < 4; i++) {
#pragma unroll
                for (int j = 0; j < 4; j++) {
                    acc1[i][j] += av1[i] * wv1[j];
                    acc2[i][j] += av2[i] * wv2[j];
                }
            }
        }
        __syncthreads();
    }

    // ---- epilogue: bias + leaky-relu + sum, single float4 store per row ----
    float4 bb1 = *reinterpret_cast<const float4*>(b1 + j0 + tx * 4);
    float4 bb2 = *reinterpret_cast<const float4*>(b2 + j0 + tx * 4);
    float bv1[4] = {bb1.x, bb1.y, bb1.z, bb1.w};
    float bv2[4] = {bb2.x, bb2.y, bb2.z, bb2.w};

#pragma unroll
    for (int i = 0; i < 4; i++) {
        int gi = i0 + ty * 4 + i;
        if (gi < N_NODES) {
            float4 o;
            o.x = lrelu(acc1[i][0] + bv1[0]) + lrelu(acc2[i][0] + bv2[0]);
            o.y = lrelu(acc1[i][1] + bv1[1]) + lrelu(acc2[i][1] + bv2[1]);
            o.z = lrelu(acc1[i][2] + bv1[2]) + lrelu(acc2[i][2] + bv2[2]);
            o.w = lrelu(acc1[i][3] + bv1[3]) + lrelu(acc2[i][3] + bv2[3]);
            *reinterpret_cast<float4*>(out + (size_t)gi * D + j0 + tx * 4) = o;
        }
    }
}

// ---------------------------------------------------------------------------
// Launch: zero -> scatter -> fused gemm (all on the capture stream)
// ---------------------------------------------------------------------------
extern "C" void kernel_launch(void* const* d_in, const int* in_sizes, int n_in,
                              void* d_out, int out_size) {
    const float* ego  = (const float*)d_in[0];
    const float* vals = (const float*)d_in[1];
    const float* W1   = (const float*)d_in[2];
    const float* b1   = (const float*)d_in[3];
    const float* W2   = (const float*)d_in[4];
    const float* b2   = (const float*)d_in[5];
    const int*   rows = (const int*)d_in[6];
    const int*   cols = (const int*)d_in[7];
    float*       out  = (float*)d_out;

    int E = in_sizes[1];

    // 1) zero side buffer: N_NODES*D/4 float4 = 6,400,000 -> 25000 blocks x 256
    zero_side_kernel<<<(N_NODES * (D / 4)) / 256, 256>>>();

    // 2) scatter: one warp per edge, 8 warps per 256-thread block
    int scatter_blocks = (E + 7) / 8;
    spmm_scatter_kernel<<<scatter_blocks, 256>>>(ego, vals, rows, cols, E);

    // 3) fused dual GEMM + epilogue
    dim3 grid((N_NODES + BM - 1) / BM, D / BN);
    fused_gemm_kernel<<<grid, 256>>>(ego, W1, b1, W2, b2, out);
}

// round 3
// speedup vs baseline: 1.1111x; 1.1111x over previous
#include <cuda_runtime.h>
#include <cstdint>

#define N_NODES 100000
#define D 256
#define E_MAX 3200000

typedef unsigned long long ull;

// ---------------- device scratch (static, per allocation rules) ------------
__device__ float g_side[(size_t)N_NODES * D];   // 102.4 MB
__device__ int   g_cnt[N_NODES];
__device__ int   g_rowstart[N_NODES + 1];
__device__ int   g_cursor[N_NODES];
__device__ int   g_colsorted[E_MAX];
__device__ float g_valsorted[E_MAX];
__device__ int   g_blocksums[128];

// ===========================================================================
// CSR build: zero -> histogram -> scan(3 kernels) -> bucket scatter
// ===========================================================================
__global__ void zero_cnt_kernel() {
    int i = blockIdx.x * blockDim.x + threadIdx.x;
    if (i < N_NODES) g_cnt[i] = 0;
}

__global__ void hist_kernel(const int* __restrict__ rows, int E) {
    int e = blockIdx.x * blockDim.x + threadIdx.x;
    if (e < E) atomicAdd(&g_cnt[rows[e]], 1);
}

#define SCAN_B 1024
// per-block inclusive scan of counts; writes per-element EXCLUSIVE scan and block sum
__global__ void scan1_kernel() {
    __shared__ int sm[SCAN_B];
    int t = threadIdx.x;
    int i = blockIdx.x * SCAN_B + t;
    int x = (i < N_NODES) ? g_cnt[i] : 0;
    int val = x;
    sm[t] = val;
    __syncthreads();
#pragma unroll
    for (int off = 1; off < SCAN_B; off <<= 1) {
        int y = (t >= off) ? sm[t - off] : 0;
        __syncthreads();
        val += y;
        sm[t] = val;
        __syncthreads();
    }
    if (i < N_NODES) g_rowstart[i] = val - x;      // exclusive within block
    if (t == SCAN_B - 1) g_blocksums[blockIdx.x] = val;
}

// exclusive scan of the (<=128) block sums, single block
__global__ void scan2_kernel(int nblocks) {
    __shared__ int sm[128];
    int t = threadIdx.x;
    int x = (t < nblocks) ? g_blocksums[t] : 0;
    int val = x;
    sm[t] = val;
    __syncthreads();
#pragma unroll
    for (int off = 1; off < 128; off <<= 1) {
        int y = (t >= off) ? sm[t - off] : 0;
        __syncthreads();
        val += y;
        sm[t] = val;
        __syncthreads();
    }
    if (t < nblocks) g_blocksums[t] = val - x;     // exclusive
}

__global__ void scan3_kernel(int E) {
    int i = blockIdx.x * SCAN_B + threadIdx.x;
    if (i < N_NODES) {
        int v = g_rowstart[i] + g_blocksums[blockIdx.x];
        g_rowstart[i] = v;
        g_cursor[i]   = v;
    }
    if (i == 0) g_rowstart[N_NODES] = E;
}

__global__ void bucket_kernel(const int* __restrict__ rows,
                              const int* __restrict__ cols,
                              const float* __restrict__ vals, int E) {
    int e = blockIdx.x * blockDim.x + threadIdx.x;
    if (e >= E) return;
    int r = rows[e];
    int p = atomicAdd(&g_cursor[r], 1);
    g_colsorted[p] = cols[e];
    g_valsorted[p] = vals[e];
}

// ===========================================================================
// Pull SpMM: one warp per row, register accumulation, no float atomics.
// Lanes cooperatively stage 32 (col,val) pairs, broadcast via shfl.
// ===========================================================================
__global__ void pull_spmm_kernel(const float* __restrict__ ego) {
    int warp = (int)((blockIdx.x * blockDim.x + threadIdx.x) >> 5);
    if (warp >= N_NODES) return;
    int lane = threadIdx.x & 31;

    int s = g_rowstart[warp];
    int e = g_rowstart[warp + 1];

    float4 acc0 = make_float4(0.f, 0.f, 0.f, 0.f);
    float4 acc1 = make_float4(0.f, 0.f, 0.f, 0.f);
    const float4* ego4 = reinterpret_cast<const float4*>(ego);

    for (int base = s; base < e; base += 32) {
        int rem = e - base; if (rem > 32) rem = 32;
        int   c = 0;
        float v = 0.f;
        if (lane < rem) {
            c = g_colsorted[base + lane];
            v = g_valsorted[base + lane];
        }
        for (int j = 0; j < rem; j++) {
            int   cj = __shfl_sync(0xffffffffu, c, j);
            float vj = __shfl_sync(0xffffffffu, v, j);
            const float4* src = ego4 + (size_t)cj * (D / 4);
            float4 x0 = __ldg(src + lane);
            float4 x1 = __ldg(src + lane + 32);
            acc0.x = fmaf(x0.x, vj, acc0.x); acc0.y = fmaf(x0.y, vj, acc0.y);
            acc0.z = fmaf(x0.z, vj, acc0.z); acc0.w = fmaf(x0.w, vj, acc0.w);
            acc1.x = fmaf(x1.x, vj, acc1.x); acc1.y = fmaf(x1.y, vj, acc1.y);
            acc1.z = fmaf(x1.z, vj, acc1.z); acc1.w = fmaf(x1.w, vj, acc1.w);
        }
    }
    float4* dst = reinterpret_cast<float4*>(g_side) + (size_t)warp * (D / 4);
    dst[lane]      = acc0;
    dst[lane + 32] = acc1;
}

// ===========================================================================
// Fused dual GEMM + epilogue, packed f32x2 FMA (SASS FFMA2).
//   out = lrelu((ego+side)@W1^T + b1) + lrelu((ego*side)@W2^T + b2)
// BM=64, BN=128, BK=16, 256 threads, 4x8 microtile per path.
// ===========================================================================
#define GBM 64
#define GBN 128
#define GBK 16
#define PA (GBM + 4)
#define PW (GBN + 4)

__device__ __forceinline__ float lrelu(float x) { return x > 0.f ? x : 0.01f * x; }

__device__ __forceinline__ void fma2(ull& acc, ull a, ull b) {
    asm("fma.rn.f32x2 %0, %1, %2, %0;" : "+l"(acc) : "l"(a), "l"(b));
}
__device__ __forceinline__ ull pack2(float x) {
    ull r;
    asm("mov.b64 %0, {%1, %1};" : "=l"(r) : "f"(x));
    return r;
}
__device__ __forceinline__ float2 unpack2(ull a) {
    float2 f;
    asm("mov.b64 {%0, %1}, %2;" : "=f"(f.x), "=f"(f.y) : "l"(a));
    return f;
}

__global__ __launch_bounds__(256) void fused_gemm_kernel(
    const float* __restrict__ ego,
    const float* __restrict__ W1, const float* __restrict__ b1,
    const float* __restrict__ W2, const float* __restrict__ b2,
    float* __restrict__ out) {

    __shared__ __align__(16) float sA1[GBK][PA];
    __shared__ __align__(16) float sA2[GBK][PA];
    __shared__ __align__(16) float sW1[GBK][PW];
    __shared__ __align__(16) float sW2[GBK][PW];

    int t  = threadIdx.x;
    int i0 = blockIdx.x * GBM;
    int j0 = blockIdx.y * GBN;

    // A loader: 64 rows x 16 k, one float4 per thread
    int lr = t >> 2;
    int lk = (t & 3) * 4;
    // W loader: 128 rows x 16 k, two float4 per W per thread
    int wr = t >> 1;
    int wk = (t & 1) * 8;
    // compute: 16x16 threads, 4 rows x 8 cols (4 f32x2 pairs) per path
    int ty = t >> 4;
    int tx = t & 15;

    bool aval = (i0 + lr) < N_NODES;
    const float* pe = ego    + (size_t)(i0 + lr) * D + lk;
    const float* ps = g_side + (size_t)(i0 + lr) * D + lk;
    const float* pw1 = W1 + (size_t)(j0 + wr) * D + wk;
    const float* pw2 = W2 + (size_t)(j0 + wr) * D + wk;

    float4 re, rs, rw1a, rw1b, rw2a, rw2b;
    const float4 z4 = make_float4(0.f, 0.f, 0.f, 0.f);

    // prefetch tile 0
    re   = aval ? *reinterpret_cast<const float4*>(pe) : z4;
    rs   = aval ? *reinterpret_cast<const float4*>(ps) : z4;
    rw1a = *reinterpret_cast<const float4*>(pw1);
    rw1b = *reinterpret_cast<const float4*>(pw1 + 4);
    rw2a = *reinterpret_cast<const float4*>(pw2);
    rw2b = *reinterpret_cast<const float4*>(pw2 + 4);

    ull acc1[4][4] = {}, acc2[4][4] = {};

    for (int k0 = 0; k0 < D; k0 += GBK) {
        // commit prefetched regs to smem
        sA1[lk + 0][lr] = re.x + rs.x;  sA2[lk + 0][lr] = re.x * rs.x;
        sA1[lk + 1][lr] = re.y + rs.y;  sA2[lk + 1][lr] = re.y * rs.y;
        sA1[lk + 2][lr] = re.z + rs.z;  sA2[lk + 2][lr] = re.z * rs.z;
        sA1[lk + 3][lr] = re.w + rs.w;  sA2[lk + 3][lr] = re.w * rs.w;
        sW1[wk + 0][wr] = rw1a.x; sW1[wk + 1][wr] = rw1a.y;
        sW1[wk + 2][wr] = rw1a.z; sW1[wk + 3][wr] = rw1a.w;
        sW1[wk + 4][wr] = rw1b.x; sW1[wk + 5][wr] = rw1b.y;
        sW1[wk + 6][wr] = rw1b.z; sW1[wk + 7][wr] = rw1b.w;
        sW2[wk + 0][wr] = rw2a.x; sW2[wk + 1][wr] = rw2a.y;
        sW2[wk + 2][wr] = rw2a.z; sW2[wk + 3][wr] = rw2a.w;
        sW2[wk + 4][wr] = rw2b.x; sW2[wk + 5][wr] = rw2b.y;
        sW2[wk + 6][wr] = rw2b.z; sW2[wk + 7][wr] = rw2b.w;
        __syncthreads();

        // prefetch next tile while computing this one
        if (k0 + GBK < D) {
            re   = aval ? *reinterpret_cast<const float4*>(pe + k0 + GBK) : z4;
            rs   = aval ? *reinterpret_cast<const float4*>(ps + k0 + GBK) : z4;
            rw1a = *reinterpret_cast<const float4*>(pw1 + k0 + GBK);
            rw1b = *reinterpret_cast<const float4*>(pw1 + k0 + GBK + 4);
            rw2a = *reinterpret_cast<const float4*>(pw2 + k0 + GBK);
            rw2b = *reinterpret_cast<const float4*>(pw2 + k0 + GBK + 4);
        }

#pragma unroll
        for (int k = 0; k < GBK; k++) {
            float4 a1 = *reinterpret_cast<float4*>(&sA1[k][ty * 4]);
            float4 a2 = *reinterpret_cast<float4*>(&sA2[k][ty * 4]);
            const ull* w1p = reinterpret_cast<const ull*>(&sW1[k][tx * 8]);
            const ull* w2p = reinterpret_cast<const ull*>(&sW2[k][tx * 8]);
            ull w1r[4] = {w1p[0], w1p[1], w1p[2], w1p[3]};
            ull w2r[4] = {w2p[0], w2p[1], w2p[2], w2p[3]};
            float av1[4] = {a1.x, a1.y, a1.z, a1.w};
            float av2[4] = {a2.x, a2.y, a2.z, a2.w};
#pragma unroll
            for (int i = 0; i < 4; i++) {
                ull aa1 = pack2(av1[i]);
                ull aa2 = pack2(av2[i]);
#pragma unroll
                for (int jp = 0; jp < 4; jp++) {
                    fma2(acc1[i][jp], aa1, w1r[jp]);
                    fma2(acc2[i][jp], aa2, w2r[jp]);
                }
            }
        }
        __syncthreads();
    }

    // epilogue: bias + leaky-relu + combine, 2 float4 stores per row
    float b1v[8], b2v[8];
#pragma unroll
    for (int q = 0; q < 8; q++) {
        b1v[q] = b1[j0 + tx * 8 + q];
        b2v[q] = b2[j0 + tx * 8 + q];
    }
#pragma unroll
    for (int i = 0; i < 4; i++) {
        int gi = i0 + ty * 4 + i;
        if (gi >= N_NODES) continue;
        float o[8];
#pragma unroll
        for (int jp = 0; jp < 4; jp++) {
            float2 u1 = unpack2(acc1[i][jp]);
            float2 u2 = unpack2(acc2[i][jp]);
            o[jp * 2 + 0] = lrelu(u1.x + b1v[jp * 2 + 0]) + lrelu(u2.x + b2v[jp * 2 + 0]);
            o[jp * 2 + 1] = lrelu(u1.y + b1v[jp * 2 + 1]) + lrelu(u2.y + b2v[jp * 2 + 1]);
        }
        float* po = out + (size_t)gi * D + j0 + tx * 8;
        *reinterpret_cast<float4*>(po)     = make_float4(o[0], o[1], o[2], o[3]);
        *reinterpret_cast<float4*>(po + 4) = make_float4(o[4], o[5], o[6], o[7]);
    }
}

// ===========================================================================
// Launch sequence (all graph-capturable, stream-ordered)
// ===========================================================================
extern "C" void kernel_launch(void* const* d_in, const int* in_sizes, int n_in,
                              void* d_out, int out_size) {
    const float* ego  = (const float*)d_in[0];
    const float* vals = (const float*)d_in[1];
    const float* W1   = (const float*)d_in[2];
    const float* b1   = (const float*)d_in[3];
    const float* W2   = (const float*)d_in[4];
    const float* b2   = (const float*)d_in[5];
    const int*   rows = (const int*)d_in[6];
    const int*   cols = (const int*)d_in[7];
    float*       out  = (float*)d_out;

    int E = in_sizes[1];
    int scan_blocks = (N_NODES + SCAN_B - 1) / SCAN_B;   // 98

    // CSR build
    zero_cnt_kernel<<<(N_NODES + 255) / 256, 256>>>();
    hist_kernel<<<(E + 255) / 256, 256>>>(rows, E);
    scan1_kernel<<<scan_blocks, SCAN_B>>>();
    scan2_kernel<<<1, 128>>>(scan_blocks);
    scan3_kernel<<<scan_blocks, SCAN_B>>>(E);
    bucket_kernel<<<(E + 255) / 256, 256>>>(rows, cols, vals, E);

    // pull SpMM: one warp per row
    pull_spmm_kernel<<<(N_NODES * 32 + 255) / 256, 256>>>(ego);

    // fused dual GEMM + epilogue
    dim3 grid((N_NODES + GBM - 1) / GBM, D / GBN);
    fused_gemm_kernel<<<grid, 256>>>(ego, W1, b1, W2, b2, out);
}

// round 7
// speedup vs baseline: 1.9486x; 1.7538x over previous
#include <cuda_runtime.h>
#include <cuda_bf16.h>
#include <cstdint>

#define N_NODES 100000
#define D 256
#define E_MAX 3200000

typedef unsigned long long ull;

// ---------------- device scratch (static, per allocation rules) ------------
__device__ float g_side[(size_t)N_NODES * D];   // 102.4 MB
__device__ int   g_cnt[N_NODES];
__device__ int   g_rowstart[N_NODES + 1];
__device__ int   g_cursor[N_NODES];
__device__ int   g_colsorted[E_MAX];
__device__ float g_valsorted[E_MAX];
__device__ int   g_blocksums[128];
// bf16 hi/lo split of the weight matrices, K-major [n][k]
__device__ __nv_bfloat16 g_w1hi[D * D];
__device__ __nv_bfloat16 g_w1lo[D * D];
__device__ __nv_bfloat16 g_w2hi[D * D];
__device__ __nv_bfloat16 g_w2lo[D * D];

// ===========================================================================
// helpers
// ===========================================================================
__device__ __forceinline__ uint32_t smem_to_u32(const void* p) {
    uint32_t a;
    asm("{ .reg .u64 t; cvta.to.shared.u64 t, %1; cvt.u32.u64 %0, t; }"
        : "=r"(a) : "l"(p));
    return a;
}
__device__ __forceinline__ void ldm_x4(uint32_t* r, uint32_t addr) {
    asm volatile("ldmatrix.sync.aligned.m8n8.x4.shared.b16 {%0,%1,%2,%3}, [%4];"
                 : "=r"(r[0]), "=r"(r[1]), "=r"(r[2]), "=r"(r[3]) : "r"(addr));
}
__device__ __forceinline__ void ldm_x2(uint32_t* r, uint32_t addr) {
    asm volatile("ldmatrix.sync.aligned.m8n8.x2.shared.b16 {%0,%1}, [%2];"
                 : "=r"(r[0]), "=r"(r[1]) : "r"(addr));
}
__device__ __forceinline__ void mma_bf16(float* d, const uint32_t* a, const uint32_t* b) {
    asm volatile("mma.sync.aligned.m16n8k16.row.col.f32.bf16.bf16.f32 "
                 "{%0,%1,%2,%3}, {%4,%5,%6,%7}, {%8,%9}, {%0,%1,%2,%3};"
                 : "+f"(d[0]), "+f"(d[1]), "+f"(d[2]), "+f"(d[3])
                 : "r"(a[0]), "r"(a[1]), "r"(a[2]), "r"(a[3]),
                   "r"(b[0]), "r"(b[1]));
}
__device__ __forceinline__ float lrelu(float x) { return x > 0.f ? x : 0.01f * x; }

// pack 4 bf16 (from 4 floats, round-to-nearest) into one 64-bit word
__device__ __forceinline__ ull pack4(float a, float b, float c, float d) {
    unsigned short u0 = __bfloat16_as_ushort(__float2bfloat16(a));
    unsigned short u1 = __bfloat16_as_ushort(__float2bfloat16(b));
    unsigned short u2 = __bfloat16_as_ushort(__float2bfloat16(c));
    unsigned short u3 = __bfloat16_as_ushort(__float2bfloat16(d));
    return (ull)u0 | ((ull)u1 << 16) | ((ull)u2 << 32) | ((ull)u3 << 48);
}

// ===========================================================================
// CSR build: zero -> histogram -> scan(3 kernels) -> bucket scatter
// ===========================================================================
__global__ void zero_cnt_kernel() {
    int i = blockIdx.x * blockDim.x + threadIdx.x;
    if (i < N_NODES) g_cnt[i] = 0;
}

__global__ void hist_kernel(const int* __restrict__ rows, int E) {
    int e = blockIdx.x * blockDim.x + threadIdx.x;
    if (e < E) atomicAdd(&g_cnt[rows[e]], 1);
}

#define SCAN_B 1024
__global__ void scan1_kernel() {
    __shared__ int sm[SCAN_B];
    int t = threadIdx.x;
    int i = blockIdx.x * SCAN_B + t;
    int x = (i < N_NODES) ? g_cnt[i] : 0;
    int val = x;
    sm[t] = val;
    __syncthreads();
#pragma unroll
    for (int off = 1; off < SCAN_B; off <<= 1) {
        int y = (t >= off) ? sm[t - off] : 0;
        __syncthreads();
        val += y;
        sm[t] = val;
        __syncthreads();
    }
    if (i < N_NODES) g_rowstart[i] = val - x;
    if (t == SCAN_B - 1) g_blocksums[blockIdx.x] = val;
}

__global__ void scan2_kernel(int nblocks) {
    __shared__ int sm[128];
    int t = threadIdx.x;
    int x = (t < nblocks) ? g_blocksums[t] : 0;
    int val = x;
    sm[t] = val;
    __syncthreads();
#pragma unroll
    for (int off = 1; off < 128; off <<= 1) {
        int y = (t >= off) ? sm[t - off] : 0;
        __syncthreads();
        val += y;
        sm[t] = val;
        __syncthreads();
    }
    if (t < nblocks) g_blocksums[t] = val - x;
}

__global__ void scan3_kernel(int E) {
    int i = blockIdx.x * SCAN_B + threadIdx.x;
    if (i < N_NODES) {
        int v = g_rowstart[i] + g_blocksums[blockIdx.x];
        g_rowstart[i] = v;
        g_cursor[i]   = v;
    }
    if (i == 0) g_rowstart[N_NODES] = E;
}

__global__ void bucket_kernel(const int* __restrict__ rows,
                              const int* __restrict__ cols,
                              const float* __restrict__ vals, int E) {
    int e = blockIdx.x * blockDim.x + threadIdx.x;
    if (e >= E) return;
    int r = rows[e];
    int p = atomicAdd(&g_cursor[r], 1);
    g_colsorted[p] = cols[e];
    g_valsorted[p] = vals[e];
}

// ===========================================================================
// Pull SpMM: one warp per row, register accumulation, no float atomics.
// ===========================================================================
__global__ void pull_spmm_kernel(const float* __restrict__ ego) {
    int warp = (int)((blockIdx.x * blockDim.x + threadIdx.x) >> 5);
    if (warp >= N_NODES) return;
    int lane = threadIdx.x & 31;

    int s = g_rowstart[warp];
    int e = g_rowstart[warp + 1];

    float4 acc0 = make_float4(0.f, 0.f, 0.f, 0.f);
    float4 acc1 = make_float4(0.f, 0.f, 0.f, 0.f);
    const float4* ego4 = reinterpret_cast<const float4*>(ego);

    for (int base = s; base < e; base += 32) {
        int rem = e - base; if (rem > 32) rem = 32;
        int   c = 0;
        float v = 0.f;
        if (lane < rem) {
            c = g_colsorted[base + lane];
            v = g_valsorted[base + lane];
        }
        for (int j = 0; j < rem; j++) {
            int   cj = __shfl_sync(0xffffffffu, c, j);
            float vj = __shfl_sync(0xffffffffu, v, j);
            const float4* src = ego4 + (size_t)cj * (D / 4);
            float4 x0 = __ldg(src + lane);
            float4 x1 = __ldg(src + lane + 32);
            acc0.x = fmaf(x0.x, vj, acc0.x); acc0.y = fmaf(x0.y, vj, acc0.y);
            acc0.z = fmaf(x0.z, vj, acc0.z); acc0.w = fmaf(x0.w, vj, acc0.w);
            acc1.x = fmaf(x1.x, vj, acc1.x); acc1.y = fmaf(x1.y, vj, acc1.y);
            acc1.z = fmaf(x1.z, vj, acc1.z); acc1.w = fmaf(x1.w, vj, acc1.w);
        }
    }
    float4* dst = reinterpret_cast<float4*>(g_side) + (size_t)warp * (D / 4);
    dst[lane]      = acc0;
    dst[lane + 32] = acc1;
}

// ===========================================================================
// W split: fp32 -> bf16 hi + bf16 lo (exact residual capture)
// ===========================================================================
__global__ void wsplit_kernel(const float* __restrict__ W1,
                              const float* __restrict__ W2) {
    int i = blockIdx.x * blockDim.x + threadIdx.x;
    if (i >= D * D) return;
    float w1 = W1[i];
    __nv_bfloat16 h1 = __float2bfloat16(w1);
    g_w1hi[i] = h1;
    g_w1lo[i] = __float2bfloat16(w1 - __bfloat162float(h1));
    float w2 = W2[i];
    __nv_bfloat16 h2 = __float2bfloat16(w2);
    g_w2hi[i] = h2;
    g_w2lo[i] = __float2bfloat16(w2 - __bfloat162float(h2));
}

// ===========================================================================
// HMMA dual GEMM (bf16 3-term split), fused epilogue.
//   acc1 = (ego+side) @ W1^T ; acc2 = (ego*side) @ W2^T
//   out  = lrelu(acc1+b1) + lrelu(acc2+b2)
// CTA: 128m x 64n, 8 warps (4m x 2n), warp tile 32x32, BK=32, 8 chunks.
// smem rows padded to 80B -> conflict-free ldmatrix.
// ===========================================================================
#define RSTRIDE 80
#define A_BUF (128 * RSTRIDE)       // 10240
#define W_BUF (64 * RSTRIDE)        // 5120
#define OFF_A1H 0
#define OFF_A1L (OFF_A1H + A_BUF)
#define OFF_A2H (OFF_A1L + A_BUF)
#define OFF_A2L (OFF_A2H + A_BUF)
#define OFF_W1H (OFF_A2L + A_BUF)
#define OFF_W1L (OFF_W1H + W_BUF)
#define OFF_W2H (OFF_W1L + W_BUF)
#define OFF_W2L (OFF_W2H + W_BUF)
#define SM_TOTAL (OFF_W2L + W_BUF)  // 61440 bytes

__global__ void __launch_bounds__(256, 1) gemm_mma_kernel(
    const float* __restrict__ ego,
    const float* __restrict__ b1, const float* __restrict__ b2,
    float* __restrict__ out) {

    extern __shared__ char smem[];
    uint32_t sb = smem_to_u32(smem);
    int t    = threadIdx.x;
    int lane = t & 31;
    int wid  = t >> 5;
    int row0 = blockIdx.x * 128;
    int j0   = blockIdx.y * 64;
    int mw   = (wid & 3) * 32;       // warp m origin in tile
    int nw   = (wid >> 2) * 32;      // warp n origin in tile

    // lane components for ldmatrix addressing
    int mloc = (lane & 7) + ((lane >> 3) & 1) * 8;
    int akb  = ((lane >> 4) & 1) * 16;    // k-block byte offset (A, x4)
    int nloc = lane & 7;
    int bkb  = ((lane >> 3) & 1) * 16;    // k-block byte offset (B, x2)

    float acc1[2][4][4] = {}, acc2[2][4][4] = {};

    for (int ch = 0; ch < 8; ch++) {
        int k0 = ch * 32;

        // ---- A: load ego/side, build a1/a2 hi/lo bf16 tiles (128 x 32) ----
#pragma unroll
        for (int s = 0; s < 4; s++) {
            int idx = s * 256 + t;
            int r   = idx >> 3;
            int k4  = idx & 7;
            int gr  = row0 + r;
            float4 e4 = make_float4(0.f, 0.f, 0.f, 0.f);
            float4 s4 = e4;
            if (gr < N_NODES) {
                e4 = *reinterpret_cast<const float4*>(ego    + (size_t)gr * D + k0 + k4 * 4);
                s4 = *reinterpret_cast<const float4*>(g_side + (size_t)gr * D + k0 + k4 * 4);
            }
            float a1[4] = {e4.x + s4.x, e4.y + s4.y, e4.z + s4.z, e4.w + s4.w};
            float a2[4] = {e4.x * s4.x, e4.y * s4.y, e4.z * s4.z, e4.w * s4.w};
            float h1[4], h2[4];
#pragma unroll
            for (int q = 0; q < 4; q++) {
                h1[q] = __bfloat162float(__float2bfloat16(a1[q]));
                h2[q] = __bfloat162float(__float2bfloat16(a2[q]));
            }
            int off = r * RSTRIDE + k4 * 8;
            *reinterpret_cast<ull*>(smem + OFF_A1H + off) = pack4(h1[0], h1[1], h1[2], h1[3]);
            *reinterpret_cast<ull*>(smem + OFF_A1L + off) =
                pack4(a1[0] - h1[0], a1[1] - h1[1], a1[2] - h1[2], a1[3] - h1[3]);
            *reinterpret_cast<ull*>(smem + OFF_A2H + off) = pack4(h2[0], h2[1], h2[2], h2[3]);
            *reinterpret_cast<ull*>(smem + OFF_A2L + off) =
                pack4(a2[0] - h2[0], a2[1] - h2[1], a2[2] - h2[2], a2[3] - h2[3]);
        }

        // ---- W: copy 64 x 32 bf16 tiles (already split) ----
        {
            int n  = t >> 2;
            int kc = t & 3;
            size_t src = (size_t)(j0 + n) * D + k0 + kc * 8;
            int dst = n * RSTRIDE + kc * 16;
            *reinterpret_cast<uint4*>(smem + OFF_W1H + dst) =
                *reinterpret_cast<const uint4*>(g_w1hi + src);
            *reinterpret_cast<uint4*>(smem + OFF_W1L + dst) =
                *reinterpret_cast<const uint4*>(g_w1lo + src);
            *reinterpret_cast<uint4*>(smem + OFF_W2H + dst) =
                *reinterpret_cast<const uint4*>(g_w2hi + src);
            *reinterpret_cast<uint4*>(smem + OFF_W2L + dst) =
                *reinterpret_cast<const uint4*>(g_w2lo + src);
        }
        __syncthreads();

        // ---- MMA: 2 k-steps of 16 ----
#pragma unroll
        for (int ks = 0; ks < 2; ks++) {
            int kb = ks * 32;   // byte offset of this k16 within a row

            uint32_t af1[2][2][4], af2[2][2][4];   // [hl][msub][4]
            uint32_t bf1[2][4][2], bf2[2][4][2];   // [hl][nsub][2]
#pragma unroll
            for (int ms = 0; ms < 2; ms++) {
                uint32_t arow = (uint32_t)((mw + ms * 16 + mloc) * RSTRIDE + kb + akb);
                ldm_x4(af1[0][ms], sb + OFF_A1H + arow);
                ldm_x4(af1[1][ms], sb + OFF_A1L + arow);
                ldm_x4(af2[0][ms], sb + OFF_A2H + arow);
                ldm_x4(af2[1][ms], sb + OFF_A2L + arow);
            }
#pragma unroll
            for (int ns = 0; ns < 4; ns++) {
                uint32_t brow = (uint32_t)((nw + ns * 8 + nloc) * RSTRIDE + kb + bkb);
                ldm_x2(bf1[0][ns], sb + OFF_W1H + brow);
                ldm_x2(bf1[1][ns], sb + OFF_W1L + brow);
                ldm_x2(bf2[0][ns], sb + OFF_W2H + brow);
                ldm_x2(bf2[1][ns], sb + OFF_W2L + brow);
            }
#pragma unroll
            for (int ms = 0; ms < 2; ms++) {
#pragma unroll
                for (int ns = 0; ns < 4; ns++) {
                    // path 1: hi*hi + hi*lo + lo*hi
                    mma_bf16(acc1[ms][ns], af1[0][ms], bf1[0][ns]);
                    mma_bf16(acc1[ms][ns], af1[0][ms], bf1[1][ns]);
                    mma_bf16(acc1[ms][ns], af1[1][ms], bf1[0][ns]);
                    // path 2
                    mma_bf16(acc2[ms][ns], af2[0][ms], bf2[0][ns]);
                    mma_bf16(acc2[ms][ns], af2[0][ms], bf2[1][ns]);
                    mma_bf16(acc2[ms][ns], af2[1][ms], bf2[0][ns]);
                }
            }
        }
        __syncthreads();
    }

    // ---- epilogue ----
    float2 b1v[4], b2v[4];
#pragma unroll
    for (int ns = 0; ns < 4; ns++) {
        int ng = j0 + nw + ns * 8 + 2 * (lane & 3);
        b1v[ns] = *reinterpret_cast<const float2*>(b1 + ng);
        b2v[ns] = *reinterpret_cast<const float2*>(b2 + ng);
    }
#pragma unroll
    for (int ms = 0; ms < 2; ms++) {
#pragma unroll
        for (int h = 0; h < 2; h++) {
            int gm = row0 + mw + ms * 16 + (lane >> 2) + h * 8;
            if (gm < N_NODES) {
#pragma unroll
                for (int ns = 0; ns < 4; ns++) {
                    int ng = j0 + nw + ns * 8 + 2 * (lane & 3);
                    float2 o;
                    o.x = lrelu(acc1[ms][ns][h * 2 + 0] + b1v[ns].x) +
                          lrelu(acc2[ms][ns][h * 2 + 0] + b2v[ns].x);
                    o.y = lrelu(acc1[ms][ns][h * 2 + 1] + b1v[ns].y) +
                          lrelu(acc2[ms][ns][h * 2 + 1] + b2v[ns].y);
                    *reinterpret_cast<float2*>(out + (size_t)gm * D + ng) = o;
                }
            }
        }
    }
}

// ===========================================================================
// Launch sequence (all graph-capturable, stream-ordered)
// ===========================================================================
extern "C" void kernel_launch(void* const* d_in, const int* in_sizes, int n_in,
                              void* d_out, int out_size) {
    const float* ego  = (const float*)d_in[0];
    const float* vals = (const float*)d_in[1];
    const float* W1   = (const float*)d_in[2];
    const float* b1   = (const float*)d_in[3];
    const float* W2   = (const float*)d_in[4];
    const float* b2   = (const float*)d_in[5];
    const int*   rows = (const int*)d_in[6];
    const int*   cols = (const int*)d_in[7];
    float*       out  = (float*)d_out;

    int E = in_sizes[1];
    int scan_blocks = (N_NODES + SCAN_B - 1) / SCAN_B;   // 98

    // weight split (independent of everything else)
    wsplit_kernel<<<(D * D + 255) / 256, 256>>>(W1, W2);

    // CSR build
    zero_cnt_kernel<<<(N_NODES + 255) / 256, 256>>>();
    hist_kernel<<<(E + 255) / 256, 256>>>(rows, E);
    scan1_kernel<<<scan_blocks, SCAN_B>>>();
    scan2_kernel<<<1, 128>>>(scan_blocks);
    scan3_kernel<<<scan_blocks, SCAN_B>>>(E);
    bucket_kernel<<<(E + 255) / 256, 256>>>(rows, cols, vals, E);

    // pull SpMM: one warp per row
    pull_spmm_kernel<<<(N_NODES * 32 + 255) / 256, 256>>>(ego);

    // HMMA dual GEMM + fused epilogue
    cudaFuncSetAttribute(gemm_mma_kernel,
                         cudaFuncAttributeMaxDynamicSharedMemorySize, SM_TOTAL);
    dim3 grid((N_NODES + 127) / 128, D / 64);   // 782 x 4
    gemm_mma_kernel<<<grid, 256, SM_TOTAL>>>(ego, b1, b2, out);
}

// round 8
// speedup vs baseline: 2.3440x; 1.2029x over previous
#include <cuda_runtime.h>
#include <cuda_bf16.h>
#include <cstdint>

#define N_NODES 100000
#define D 256
#define E_MAX 3200000

typedef unsigned long long ull;

// ---------------- device scratch (static, per allocation rules) ------------
__device__ int   g_cnt[N_NODES];
__device__ int   g_rowstart[N_NODES + 1];
__device__ int   g_cursor[N_NODES];
__device__ int2  g_edges[E_MAX];               // interleaved (col, val-bits)
__device__ int   g_blocksums[128];
// bf16 hi/lo split of weights, K-major [n][k]
__device__ __nv_bfloat16 g_w1hi[D * D];
__device__ __nv_bfloat16 g_w1lo[D * D];
__device__ __nv_bfloat16 g_w2hi[D * D];
__device__ __nv_bfloat16 g_w2lo[D * D];
// bf16 hi/lo split of the two GEMM A-operands, produced by pull_spmm
__device__ __nv_bfloat16 g_a1hi[(size_t)N_NODES * D];
__device__ __nv_bfloat16 g_a1lo[(size_t)N_NODES * D];
__device__ __nv_bfloat16 g_a2hi[(size_t)N_NODES * D];
__device__ __nv_bfloat16 g_a2lo[(size_t)N_NODES * D];

// ===========================================================================
// helpers
// ===========================================================================
__device__ __forceinline__ uint32_t smem_to_u32(const void* p) {
    uint32_t a;
    asm("{ .reg .u64 t; cvta.to.shared.u64 t, %1; cvt.u32.u64 %0, t; }"
        : "=r"(a) : "l"(p));
    return a;
}
__device__ __forceinline__ void ldm_x4(uint32_t* r, uint32_t addr) {
    asm volatile("ldmatrix.sync.aligned.m8n8.x4.shared.b16 {%0,%1,%2,%3}, [%4];"
                 : "=r"(r[0]), "=r"(r[1]), "=r"(r[2]), "=r"(r[3]) : "r"(addr));
}
__device__ __forceinline__ void ldm_x2(uint32_t* r, uint32_t addr) {
    asm volatile("ldmatrix.sync.aligned.m8n8.x2.shared.b16 {%0,%1}, [%2];"
                 : "=r"(r[0]), "=r"(r[1]) : "r"(addr));
}
__device__ __forceinline__ void mma_bf16(float* d, const uint32_t* a, const uint32_t* b) {
    asm volatile("mma.sync.aligned.m16n8k16.row.col.f32.bf16.bf16.f32 "
                 "{%0,%1,%2,%3}, {%4,%5,%6,%7}, {%8,%9}, {%0,%1,%2,%3};"
                 : "+f"(d[0]), "+f"(d[1]), "+f"(d[2]), "+f"(d[3])
                 : "r"(a[0]), "r"(a[1]), "r"(a[2]), "r"(a[3]),
                   "r"(b[0]), "r"(b[1]));
}
__device__ __forceinline__ float lrelu(float x) { return x > 0.f ? x : 0.01f * x; }

// pack 4 floats -> 4 bf16 (rn) in one 64-bit word
__device__ __forceinline__ ull pack4(float a, float b, float c, float d) {
    unsigned short u0 = __bfloat16_as_ushort(__float2bfloat16(a));
    unsigned short u1 = __bfloat16_as_ushort(__float2bfloat16(b));
    unsigned short u2 = __bfloat16_as_ushort(__float2bfloat16(c));
    unsigned short u3 = __bfloat16_as_ushort(__float2bfloat16(d));
    return (ull)u0 | ((ull)u1 << 16) | ((ull)u2 << 32) | ((ull)u3 << 48);
}

// ===========================================================================
// CSR build: zero -> histogram -> scan(3 kernels) -> bucket scatter
// ===========================================================================
__global__ void zero_cnt_kernel() {
    int i = blockIdx.x * blockDim.x + threadIdx.x;
    if (i < N_NODES) g_cnt[i] = 0;
}

__global__ void hist_kernel(const int* __restrict__ rows, int E) {
    int e = blockIdx.x * blockDim.x + threadIdx.x;
    if (e < E) atomicAdd(&g_cnt[rows[e]], 1);
}

#define SCAN_B 1024
__global__ void scan1_kernel() {
    __shared__ int sm[SCAN_B];
    int t = threadIdx.x;
    int i = blockIdx.x * SCAN_B + t;
    int x = (i < N_NODES) ? g_cnt[i] : 0;
    int val = x;
    sm[t] = val;
    __syncthreads();
#pragma unroll
    for (int off = 1; off < SCAN_B; off <<= 1) {
        int y = (t >= off) ? sm[t - off] : 0;
        __syncthreads();
        val += y;
        sm[t] = val;
        __syncthreads();
    }
    if (i < N_NODES) g_rowstart[i] = val - x;
    if (t == SCAN_B - 1) g_blocksums[blockIdx.x] = val;
}

__global__ void scan2_kernel(int nblocks) {
    __shared__ int sm[128];
    int t = threadIdx.x;
    int x = (t < nblocks) ? g_blocksums[t] : 0;
    int val = x;
    sm[t] = val;
    __syncthreads();
#pragma unroll
    for (int off = 1; off < 128; off <<= 1) {
        int y = (t >= off) ? sm[t - off] : 0;
        __syncthreads();
        val += y;
        sm[t] = val;
        __syncthreads();
    }
    if (t < nblocks) g_blocksums[t] = val - x;
}

__global__ void scan3_kernel(int E) {
    int i = blockIdx.x * SCAN_B + threadIdx.x;
    if (i < N_NODES) {
        int v = g_rowstart[i] + g_blocksums[blockIdx.x];
        g_rowstart[i] = v;
        g_cursor[i]   = v;
    }
    if (i == 0) g_rowstart[N_NODES] = E;
}

__global__ void bucket_kernel(const int* __restrict__ rows,
                              const int* __restrict__ cols,
                              const float* __restrict__ vals, int E) {
    int e = blockIdx.x * blockDim.x + threadIdx.x;
    if (e >= E) return;
    int r = rows[e];
    int p = atomicAdd(&g_cursor[r], 1);
    g_edges[p] = make_int2(cols[e], __float_as_int(vals[e]));
}

// ===========================================================================
// Pull SpMM + A-operand producer. One warp per row:
//  - accumulate side[row] in registers (no float atomics)
//  - then a1 = ego+side, a2 = ego*side, split fp32 -> bf16 hi+lo,
//    store 4 bf16 row buffers consumed directly by the GEMM.
// ===========================================================================
__global__ void pull_spmm_kernel(const float* __restrict__ ego) {
    int row = (int)((blockIdx.x * blockDim.x + threadIdx.x) >> 5);
    if (row >= N_NODES) return;
    int lane = threadIdx.x & 31;

    int s = g_rowstart[row];
    int e = g_rowstart[row + 1];

    float4 acc0 = make_float4(0.f, 0.f, 0.f, 0.f);
    float4 acc1 = make_float4(0.f, 0.f, 0.f, 0.f);
    const float4* ego4 = reinterpret_cast<const float4*>(ego);

    for (int base = s; base < e; base += 32) {
        int rem = e - base; if (rem > 32) rem = 32;
        int   c = 0;
        float v = 0.f;
        if (lane < rem) {
            int2 ev = g_edges[base + lane];
            c = ev.x;
            v = __int_as_float(ev.y);
        }
        for (int j = 0; j < rem; j++) {
            int   cj = __shfl_sync(0xffffffffu, c, j);
            float vj = __shfl_sync(0xffffffffu, v, j);
            const float4* src = ego4 + (size_t)cj * (D / 4);
            float4 x0 = __ldg(src + lane);
            float4 x1 = __ldg(src + lane + 32);
            acc0.x = fmaf(x0.x, vj, acc0.x); acc0.y = fmaf(x0.y, vj, acc0.y);
            acc0.z = fmaf(x0.z, vj, acc0.z); acc0.w = fmaf(x0.w, vj, acc0.w);
            acc1.x = fmaf(x1.x, vj, acc1.x); acc1.y = fmaf(x1.y, vj, acc1.y);
            acc1.z = fmaf(x1.z, vj, acc1.z); acc1.w = fmaf(x1.w, vj, acc1.w);
        }
    }

    // ---- produce a1/a2 hi/lo bf16 rows ----
    const float4* erow = ego4 + (size_t)row * (D / 4);
    float4 e0 = __ldg(erow + lane);
    float4 e1 = __ldg(erow + lane + 32);

#pragma unroll
    for (int g = 0; g < 2; g++) {
        float4 ee = g ? e1 : e0;
        float4 ss = g ? acc1 : acc0;
        float a1[4] = {ee.x + ss.x, ee.y + ss.y, ee.z + ss.z, ee.w + ss.w};
        float a2[4] = {ee.x * ss.x, ee.y * ss.y, ee.z * ss.z, ee.w * ss.w};
        float h1[4], h2[4];
#pragma unroll
        for (int q = 0; q < 4; q++) {
            h1[q] = __bfloat162float(__float2bfloat16(a1[q]));
            h2[q] = __bfloat162float(__float2bfloat16(a2[q]));
        }
        size_t off = (size_t)row * D + g * 128 + lane * 4;
        *reinterpret_cast<ull*>(g_a1hi + off) = pack4(h1[0], h1[1], h1[2], h1[3]);
        *reinterpret_cast<ull*>(g_a1lo + off) =
            pack4(a1[0] - h1[0], a1[1] - h1[1], a1[2] - h1[2], a1[3] - h1[3]);
        *reinterpret_cast<ull*>(g_a2hi + off) = pack4(h2[0], h2[1], h2[2], h2[3]);
        *reinterpret_cast<ull*>(g_a2lo + off) =
            pack4(a2[0] - h2[0], a2[1] - h2[1], a2[2] - h2[2], a2[3] - h2[3]);
    }
}

// ===========================================================================
// W split: fp32 -> bf16 hi + bf16 lo
// ===========================================================================
__global__ void wsplit_kernel(const float* __restrict__ W1,
                              const float* __restrict__ W2) {
    int i = blockIdx.x * blockDim.x + threadIdx.x;
    if (i >= D * D) return;
    float w1 = W1[i];
    __nv_bfloat16 h1 = __float2bfloat16(w1);
    g_w1hi[i] = h1;
    g_w1lo[i] = __float2bfloat16(w1 - __bfloat162float(h1));
    float w2 = W2[i];
    __nv_bfloat16 h2 = __float2bfloat16(w2);
    g_w2hi[i] = h2;
    g_w2lo[i] = __float2bfloat16(w2 - __bfloat162float(h2));
}

// ===========================================================================
// HMMA dual GEMM (bf16 3-term split), A tiles pre-split -> pure copies.
// CTA: 128m x 64n, 8 warps (4m x 2n), warp tile 32x32, BK=32, 8 chunks.
// smem rows padded to 80B -> conflict-free ldmatrix.
// ===========================================================================
#define RSTRIDE 80
#define A_BUF (128 * RSTRIDE)       // 10240
#define W_BUF (64 * RSTRIDE)        // 5120
#define OFF_A1H 0
#define OFF_A1L (OFF_A1H + A_BUF)
#define OFF_A2H (OFF_A1L + A_BUF)
#define OFF_A2L (OFF_A2H + A_BUF)
#define OFF_W1H (OFF_A2L + A_BUF)
#define OFF_W1L (OFF_W1H + W_BUF)
#define OFF_W2H (OFF_W1L + W_BUF)
#define OFF_W2L (OFF_W2H + W_BUF)
#define SM_TOTAL (OFF_W2L + W_BUF)  // 61440 bytes

__global__ void __launch_bounds__(256) gemm_mma_kernel(
    const float* __restrict__ b1, const float* __restrict__ b2,
    float* __restrict__ out) {

    extern __shared__ char smem[];
    uint32_t sb = smem_to_u32(smem);
    int t    = threadIdx.x;
    int lane = t & 31;
    int wid  = t >> 5;
    int row0 = blockIdx.x * 128;
    int j0   = blockIdx.y * 64;
    int mw   = (wid & 3) * 32;       // warp m origin in tile
    int nw   = (wid >> 2) * 32;      // warp n origin in tile

    // lane components for ldmatrix addressing
    int mloc = (lane & 7) + ((lane >> 3) & 1) * 8;
    int akb  = ((lane >> 4) & 1) * 16;    // k-block byte offset (A, x4)
    int nloc = lane & 7;
    int bkb  = ((lane >> 3) & 1) * 16;    // k-block byte offset (B, x2)

    float acc1[2][4][4] = {}, acc2[2][4][4] = {};

    for (int ch = 0; ch < 8; ch++) {
        int k0 = ch * 32;

        // ---- A: pure uint4 copies of the 4 pre-split tiles (128 x 32) ----
#pragma unroll
        for (int s = 0; s < 2; s++) {
            int idx = s * 256 + t;       // 0..511
            int r   = idx >> 2;          // 0..127
            int kc  = idx & 3;           // 16B chunk within 64B row-slice
            int gr  = row0 + r;
            int dst = r * RSTRIDE + kc * 16;
            uint4 v1h = make_uint4(0, 0, 0, 0), v1l = v1h, v2h = v1h, v2l = v1h;
            if (gr < N_NODES) {
                size_t src = (size_t)gr * D + k0 + kc * 8;
                v1h = *reinterpret_cast<const uint4*>(g_a1hi + src);
                v1l = *reinterpret_cast<const uint4*>(g_a1lo + src);
                v2h = *reinterpret_cast<const uint4*>(g_a2hi + src);
                v2l = *reinterpret_cast<const uint4*>(g_a2lo + src);
            }
            *reinterpret_cast<uint4*>(smem + OFF_A1H + dst) = v1h;
            *reinterpret_cast<uint4*>(smem + OFF_A1L + dst) = v1l;
            *reinterpret_cast<uint4*>(smem + OFF_A2H + dst) = v2h;
            *reinterpret_cast<uint4*>(smem + OFF_A2L + dst) = v2l;
        }

        // ---- W: copy 64 x 32 bf16 tiles (already split) ----
        {
            int n  = t >> 2;
            int kc = t & 3;
            size_t src = (size_t)(j0 + n) * D + k0 + kc * 8;
            int dst = n * RSTRIDE + kc * 16;
            *reinterpret_cast<uint4*>(smem + OFF_W1H + dst) =
                *reinterpret_cast<const uint4*>(g_w1hi + src);
            *reinterpret_cast<uint4*>(smem + OFF_W1L + dst) =
                *reinterpret_cast<const uint4*>(g_w1lo + src);
            *reinterpret_cast<uint4*>(smem + OFF_W2H + dst) =
                *reinterpret_cast<const uint4*>(g_w2hi + src);
            *reinterpret_cast<uint4*>(smem + OFF_W2L + dst) =
                *reinterpret_cast<const uint4*>(g_w2lo + src);
        }
        __syncthreads();

        // ---- MMA: 2 k-steps of 16 ----
#pragma unroll
        for (int ks = 0; ks < 2; ks++) {
            int kb = ks * 32;   // byte offset of this k16 within a row

            uint32_t af1[2][2][4], af2[2][2][4];   // [hl][msub][4]
            uint32_t bf1[2][4][2], bf2[2][4][2];   // [hl][nsub][2]
#pragma unroll
            for (int ms = 0; ms < 2; ms++) {
                uint32_t arow = (uint32_t)((mw + ms * 16 + mloc) * RSTRIDE + kb + akb);
                ldm_x4(af1[0][ms], sb + OFF_A1H + arow);
                ldm_x4(af1[1][ms], sb + OFF_A1L + arow);
                ldm_x4(af2[0][ms], sb + OFF_A2H + arow);
                ldm_x4(af2[1][ms], sb + OFF_A2L + arow);
            }
#pragma unroll
            for (int ns = 0; ns < 4; ns++) {
                uint32_t brow = (uint32_t)((nw + ns * 8 + nloc) * RSTRIDE + kb + bkb);
                ldm_x2(bf1[0][ns], sb + OFF_W1H + brow);
                ldm_x2(bf1[1][ns], sb + OFF_W1L + brow);
                ldm_x2(bf2[0][ns], sb + OFF_W2H + brow);
                ldm_x2(bf2[1][ns], sb + OFF_W2L + brow);
            }
#pragma unroll
            for (int ms = 0; ms < 2; ms++) {
#pragma unroll
                for (int ns = 0; ns < 4; ns++) {
                    // path 1: hi*hi + hi*lo + lo*hi
                    mma_bf16(acc1[ms][ns], af1[0][ms], bf1[0][ns]);
                    mma_bf16(acc1[ms][ns], af1[0][ms], bf1[1][ns]);
                    mma_bf16(acc1[ms][ns], af1[1][ms], bf1[0][ns]);
                    // path 2
                    mma_bf16(acc2[ms][ns], af2[0][ms], bf2[0][ns]);
                    mma_bf16(acc2[ms][ns], af2[0][ms], bf2[1][ns]);
                    mma_bf16(acc2[ms][ns], af2[1][ms], bf2[0][ns]);
                }
            }
        }
        __syncthreads();
    }

    // ---- epilogue ----
    float2 b1v[4], b2v[4];
#pragma unroll
    for (int ns = 0; ns < 4; ns++) {
        int ng = j0 + nw + ns * 8 + 2 * (lane & 3);
        b1v[ns] = *reinterpret_cast<const float2*>(b1 + ng);
        b2v[ns] = *reinterpret_cast<const float2*>(b2 + ng);
    }
#pragma unroll
    for (int ms = 0; ms < 2; ms++) {
#pragma unroll
        for (int h = 0; h < 2; h++) {
            int gm = row0 + mw + ms * 16 + (lane >> 2) + h * 8;
            if (gm < N_NODES) {
#pragma unroll
                for (int ns = 0; ns < 4; ns++) {
                    int ng = j0 + nw + ns * 8 + 2 * (lane & 3);
                    float2 o;
                    o.x = lrelu(acc1[ms][ns][h * 2 + 0] + b1v[ns].x) +
                          lrelu(acc2[ms][ns][h * 2 + 0] + b2v[ns].x);
                    o.y = lrelu(acc1[ms][ns][h * 2 + 1] + b1v[ns].y) +
                          lrelu(acc2[ms][ns][h * 2 + 1] + b2v[ns].y);
                    *reinterpret_cast<float2*>(out + (size_t)gm * D + ng) = o;
                }
            }
        }
    }
}

// ===========================================================================
// Launch sequence (all graph-capturable, stream-ordered)
// ===========================================================================
extern "C" void kernel_launch(void* const* d_in, const int* in_sizes, int n_in,
                              void* d_out, int out_size) {
    const float* ego  = (const float*)d_in[0];
    const float* vals = (const float*)d_in[1];
    const float* W1   = (const float*)d_in[2];
    const float* b1   = (const float*)d_in[3];
    const float* W2   = (const float*)d_in[4];
    const float* b2   = (const float*)d_in[5];
    const int*   rows = (const int*)d_in[6];
    const int*   cols = (const int*)d_in[7];
    float*       out  = (float*)d_out;

    int E = in_sizes[1];
    int scan_blocks = (N_NODES + SCAN_B - 1) / SCAN_B;   // 98

    // weight split (independent of everything else)
    wsplit_kernel<<<(D * D + 255) / 256, 256>>>(W1, W2);

    // CSR build
    zero_cnt_kernel<<<(N_NODES + 255) / 256, 256>>>();
    hist_kernel<<<(E + 255) / 256, 256>>>(rows, E);
    scan1_kernel<<<scan_blocks, SCAN_B>>>();
    scan2_kernel<<<1, 128>>>(scan_blocks);
    scan3_kernel<<<scan_blocks, SCAN_B>>>(E);
    bucket_kernel<<<(E + 255) / 256, 256>>>(rows, cols, vals, E);

    // pull SpMM + A-operand split: one warp per row
    pull_spmm_kernel<<<(N_NODES * 32 + 255) / 256, 256>>>(ego);

    // HMMA dual GEMM + fused epilogue
    cudaFuncSetAttribute(gemm_mma_kernel,
                         cudaFuncAttributeMaxDynamicSharedMemorySize, SM_TOTAL);
    dim3 grid((N_NODES + 127) / 128, D / 64);   // 782 x 4
    gemm_mma_kernel<<<grid, 256, SM_TOTAL>>>(b1, b2, out);
}

// round 9
// speedup vs baseline: 3.2868x; 1.4022x over previous
#include <cuda_runtime.h>
#include <cuda_bf16.h>
#include <cstdint>

#define N_NODES 100000
#define D 256
#define E_MAX 3200000

typedef unsigned long long ull;

// ---------------- device scratch (static, per allocation rules) ------------
__device__ int   g_cnt[N_NODES];
__device__ int   g_rowstart[N_NODES + 1];
__device__ int   g_cursor[N_NODES];
__device__ int2  g_edges[E_MAX];               // interleaved (col, val-bits)
__device__ int   g_blocksums[128];
// bf16 copy of ego for the gather (halves L2 gather traffic)
__device__ __nv_bfloat16 g_ego_bf[(size_t)N_NODES * D];
// bf16 hi/lo split of weights, K-major [n][k]  (W2: hi only)
__device__ __nv_bfloat16 g_w1hi[D * D];
__device__ __nv_bfloat16 g_w1lo[D * D];
__device__ __nv_bfloat16 g_w2hi[D * D];
// bf16 split of GEMM A-operands, produced by pull_spmm (a2: hi only)
__device__ __nv_bfloat16 g_a1hi[(size_t)N_NODES * D];
__device__ __nv_bfloat16 g_a1lo[(size_t)N_NODES * D];
__device__ __nv_bfloat16 g_a2hi[(size_t)N_NODES * D];

// ===========================================================================
// helpers
// ===========================================================================
__device__ __forceinline__ uint32_t smem_to_u32(const void* p) {
    uint32_t a;
    asm("{ .reg .u64 t; cvta.to.shared.u64 t, %1; cvt.u32.u64 %0, t; }"
        : "=r"(a) : "l"(p));
    return a;
}
__device__ __forceinline__ void ldm_x4(uint32_t* r, uint32_t addr) {
    asm volatile("ldmatrix.sync.aligned.m8n8.x4.shared.b16 {%0,%1,%2,%3}, [%4];"
                 : "=r"(r[0]), "=r"(r[1]), "=r"(r[2]), "=r"(r[3]) : "r"(addr));
}
__device__ __forceinline__ void ldm_x2(uint32_t* r, uint32_t addr) {
    asm volatile("ldmatrix.sync.aligned.m8n8.x2.shared.b16 {%0,%1}, [%2];"
                 : "=r"(r[0]), "=r"(r[1]) : "r"(addr));
}
__device__ __forceinline__ void mma_bf16(float* d, const uint32_t* a, const uint32_t* b) {
    asm volatile("mma.sync.aligned.m16n8k16.row.col.f32.bf16.bf16.f32 "
                 "{%0,%1,%2,%3}, {%4,%5,%6,%7}, {%8,%9}, {%0,%1,%2,%3};"
                 : "+f"(d[0]), "+f"(d[1]), "+f"(d[2]), "+f"(d[3])
                 : "r"(a[0]), "r"(a[1]), "r"(a[2]), "r"(a[3]),
                   "r"(b[0]), "r"(b[1]));
}
__device__ __forceinline__ float lrelu(float x) { return x > 0.f ? x : 0.01f * x; }

// pack 4 floats -> 4 bf16 (rn) in one 64-bit word
__device__ __forceinline__ ull pack4(float a, float b, float c, float d) {
    unsigned short u0 = __bfloat16_as_ushort(__float2bfloat16(a));
    unsigned short u1 = __bfloat16_as_ushort(__float2bfloat16(b));
    unsigned short u2 = __bfloat16_as_ushort(__float2bfloat16(c));
    unsigned short u3 = __bfloat16_as_ushort(__float2bfloat16(d));
    return (ull)u0 | ((ull)u1 << 16) | ((ull)u2 << 32) | ((ull)u3 << 48);
}
// exact bf16x2 -> 2 floats (shift / mask)
__device__ __forceinline__ float bf_lo(uint32_t u) { return __uint_as_float(u << 16); }
__device__ __forceinline__ float bf_hi(uint32_t u) { return __uint_as_float(u & 0xffff0000u); }

// ===========================================================================
// ego -> bf16 copy (for the gather)
// ===========================================================================
__global__ void ego_convert_kernel(const float* __restrict__ ego) {
    size_t i = ((size_t)blockIdx.x * blockDim.x + threadIdx.x) * 8;
    float4 f0 = *reinterpret_cast<const float4*>(ego + i);
    float4 f1 = *reinterpret_cast<const float4*>(ego + i + 4);
    ull w0 = pack4(f0.x, f0.y, f0.z, f0.w);
    ull w1 = pack4(f1.x, f1.y, f1.z, f1.w);
    *reinterpret_cast<ull*>(g_ego_bf + i)     = w0;
    *reinterpret_cast<ull*>(g_ego_bf + i + 4) = w1;
}

// ===========================================================================
// CSR build: zero -> histogram -> scan(3 kernels) -> bucket scatter
// ===========================================================================
__global__ void zero_cnt_kernel() {
    int i = blockIdx.x * blockDim.x + threadIdx.x;
    if (i < N_NODES) g_cnt[i] = 0;
}

__global__ void hist_kernel(const int* __restrict__ rows, int E) {
    int e = blockIdx.x * blockDim.x + threadIdx.x;
    if (e < E) atomicAdd(&g_cnt[rows[e]], 1);
}

#define SCAN_B 1024
__global__ void scan1_kernel() {
    __shared__ int sm[SCAN_B];
    int t = threadIdx.x;
    int i = blockIdx.x * SCAN_B + t;
    int x = (i < N_NODES) ? g_cnt[i] : 0;
    int val = x;
    sm[t] = val;
    __syncthreads();
#pragma unroll
    for (int off = 1; off < SCAN_B; off <<= 1) {
        int y = (t >= off) ? sm[t - off] : 0;
        __syncthreads();
        val += y;
        sm[t] = val;
        __syncthreads();
    }
    if (i < N_NODES) g_rowstart[i] = val - x;
    if (t == SCAN_B - 1) g_blocksums[blockIdx.x] = val;
}

__global__ void scan2_kernel(int nblocks) {
    __shared__ int sm[128];
    int t = threadIdx.x;
    int x = (t < nblocks) ? g_blocksums[t] : 0;
    int val = x;
    sm[t] = val;
    __syncthreads();
#pragma unroll
    for (int off = 1; off < 128; off <<= 1) {
        int y = (t >= off) ? sm[t - off] : 0;
        __syncthreads();
        val += y;
        sm[t] = val;
        __syncthreads();
    }
    if (t < nblocks) g_blocksums[t] = val - x;
}

__global__ void scan3_kernel(int E) {
    int i = blockIdx.x * SCAN_B + threadIdx.x;
    if (i < N_NODES) {
        int v = g_rowstart[i] + g_blocksums[blockIdx.x];
        g_rowstart[i] = v;
        g_cursor[i]   = v;
    }
    if (i == 0) g_rowstart[N_NODES] = E;
}

__global__ void bucket_kernel(const int* __restrict__ rows,
                              const int* __restrict__ cols,
                              const float* __restrict__ vals, int E) {
    int e = blockIdx.x * blockDim.x + threadIdx.x;
    if (e >= E) return;
    int r = rows[e];
    int p = atomicAdd(&g_cursor[r], 1);
    g_edges[p] = make_int2(cols[e], __float_as_int(vals[e]));
}

// ===========================================================================
// Pull SpMM (bf16 gather, fp32 accumulate) + A-operand producer.
// One warp per row; each lane owns 8 consecutive columns (lane*8 .. +7).
// ===========================================================================
__global__ void pull_spmm_kernel(const float* __restrict__ ego) {
    int row = (int)((blockIdx.x * blockDim.x + threadIdx.x) >> 5);
    if (row >= N_NODES) return;
    int lane = threadIdx.x & 31;

    int s = g_rowstart[row];
    int e = g_rowstart[row + 1];

    float acc[8] = {};

    for (int base = s; base < e; base += 32) {
        int rem = e - base; if (rem > 32) rem = 32;
        int   c = 0;
        float v = 0.f;
        if (lane < rem) {
            int2 ev = g_edges[base + lane];
            c = ev.x;
            v = __int_as_float(ev.y);
        }
        for (int j = 0; j < rem; j++) {
            int   cj = __shfl_sync(0xffffffffu, c, j);
            float vj = __shfl_sync(0xffffffffu, v, j);
            uint4 u = __ldg(reinterpret_cast<const uint4*>(
                          g_ego_bf + (size_t)cj * D + lane * 8));
            acc[0] = fmaf(bf_lo(u.x), vj, acc[0]);
            acc[1] = fmaf(bf_hi(u.x), vj, acc[1]);
            acc[2] = fmaf(bf_lo(u.y), vj, acc[2]);
            acc[3] = fmaf(bf_hi(u.y), vj, acc[3]);
            acc[4] = fmaf(bf_lo(u.z), vj, acc[4]);
            acc[5] = fmaf(bf_hi(u.z), vj, acc[5]);
            acc[6] = fmaf(bf_lo(u.w), vj, acc[6]);
            acc[7] = fmaf(bf_hi(u.w), vj, acc[7]);
        }
    }

    // ---- produce a1 hi/lo (compensated) and a2 hi (uncompensated) ----
    const float* erow = ego + (size_t)row * D + lane * 8;
    float4 e0 = __ldg(reinterpret_cast<const float4*>(erow));
    float4 e1 = __ldg(reinterpret_cast<const float4*>(erow + 4));
    float ev[8] = {e0.x, e0.y, e0.z, e0.w, e1.x, e1.y, e1.z, e1.w};

    float a1[8], a2[8], h1[8];
#pragma unroll
    for (int q = 0; q < 8; q++) {
        a1[q] = ev[q] + acc[q];
        a2[q] = ev[q] * acc[q];
        h1[q] = __bfloat162float(__float2bfloat16(a1[q]));
    }
    size_t off = (size_t)row * D + lane * 8;
    *reinterpret_cast<ull*>(g_a1hi + off)     = pack4(h1[0], h1[1], h1[2], h1[3]);
    *reinterpret_cast<ull*>(g_a1hi + off + 4) = pack4(h1[4], h1[5], h1[6], h1[7]);
    *reinterpret_cast<ull*>(g_a1lo + off) =
        pack4(a1[0] - h1[0], a1[1] - h1[1], a1[2] - h1[2], a1[3] - h1[3]);
    *reinterpret_cast<ull*>(g_a1lo + off + 4) =
        pack4(a1[4] - h1[4], a1[5] - h1[5], a1[6] - h1[6], a1[7] - h1[7]);
    *reinterpret_cast<ull*>(g_a2hi + off)     = pack4(a2[0], a2[1], a2[2], a2[3]);
    *reinterpret_cast<ull*>(g_a2hi + off + 4) = pack4(a2[4], a2[5], a2[6], a2[7]);
}

// ===========================================================================
// W split: W1 -> bf16 hi + lo ; W2 -> bf16 hi only
// ===========================================================================
__global__ void wsplit_kernel(const float* __restrict__ W1,
                              const float* __restrict__ W2) {
    int i = blockIdx.x * blockDim.x + threadIdx.x;
    if (i >= D * D) return;
    float w1 = W1[i];
    __nv_bfloat16 h1 = __float2bfloat16(w1);
    g_w1hi[i] = h1;
    g_w1lo[i] = __float2bfloat16(w1 - __bfloat162float(h1));
    g_w2hi[i] = __float2bfloat16(W2[i]);
}

// ===========================================================================
// HMMA dual GEMM: path1 3-term compensated, path2 hi*hi only.
// CTA: 128m x 64n, 8 warps (4m x 2n), warp tile 32x32, BK=32, 8 chunks.
// smem rows padded to 80B -> conflict-free ldmatrix.
// ===========================================================================
#define RSTRIDE 80
#define A_BUF (128 * RSTRIDE)       // 10240
#define W_BUF (64 * RSTRIDE)        // 5120
#define OFF_A1H 0
#define OFF_A1L (OFF_A1H + A_BUF)
#define OFF_A2H (OFF_A1L + A_BUF)
#define OFF_W1H (OFF_A2H + A_BUF)
#define OFF_W1L (OFF_W1H + W_BUF)
#define OFF_W2H (OFF_W1L + W_BUF)
#define SM_TOTAL (OFF_W2H + W_BUF)  // 46080 bytes

__global__ void __launch_bounds__(256) gemm_mma_kernel(
    const float* __restrict__ b1, const float* __restrict__ b2,
    float* __restrict__ out) {

    extern __shared__ char smem[];
    uint32_t sb = smem_to_u32(smem);
    int t    = threadIdx.x;
    int lane = t & 31;
    int wid  = t >> 5;
    int row0 = blockIdx.x * 128;
    int j0   = blockIdx.y * 64;
    int mw   = (wid & 3) * 32;       // warp m origin in tile
    int nw   = (wid >> 2) * 32;      // warp n origin in tile

    // lane components for ldmatrix addressing
    int mloc = (lane & 7) + ((lane >> 3) & 1) * 8;
    int akb  = ((lane >> 4) & 1) * 16;    // k-block byte offset (A, x4)
    int nloc = lane & 7;
    int bkb  = ((lane >> 3) & 1) * 16;    // k-block byte offset (B, x2)

    float acc1[2][4][4] = {}, acc2[2][4][4] = {};

    for (int ch = 0; ch < 8; ch++) {
        int k0 = ch * 32;

        // ---- A: pure uint4 copies of the 3 pre-split tiles (128 x 32) ----
#pragma unroll
        for (int s = 0; s < 2; s++) {
            int idx = s * 256 + t;       // 0..511
            int r   = idx >> 2;          // 0..127
            int kc  = idx & 3;           // 16B chunk within 64B row-slice
            int gr  = row0 + r;
            int dst = r * RSTRIDE + kc * 16;
            uint4 v1h = make_uint4(0, 0, 0, 0), v1l = v1h, v2h = v1h;
            if (gr < N_NODES) {
                size_t src = (size_t)gr * D + k0 + kc * 8;
                v1h = *reinterpret_cast<const uint4*>(g_a1hi + src);
                v1l = *reinterpret_cast<const uint4*>(g_a1lo + src);
                v2h = *reinterpret_cast<const uint4*>(g_a2hi + src);
            }
            *reinterpret_cast<uint4*>(smem + OFF_A1H + dst) = v1h;
            *reinterpret_cast<uint4*>(smem + OFF_A1L + dst) = v1l;
            *reinterpret_cast<uint4*>(smem + OFF_A2H + dst) = v2h;
        }

        // ---- W: copy 64 x 32 bf16 tiles (already split) ----
        {
            int n  = t >> 2;
            int kc = t & 3;
            size_t src = (size_t)(j0 + n) * D + k0 + kc * 8;
            int dst = n * RSTRIDE + kc * 16;
            *reinterpret_cast<uint4*>(smem + OFF_W1H + dst) =
                *reinterpret_cast<const uint4*>(g_w1hi + src);
            *reinterpret_cast<uint4*>(smem + OFF_W1L + dst) =
                *reinterpret_cast<const uint4*>(g_w1lo + src);
            *reinterpret_cast<uint4*>(smem + OFF_W2H + dst) =
                *reinterpret_cast<const uint4*>(g_w2hi + src);
        }
        __syncthreads();

        // ---- MMA: 2 k-steps of 16 ----
#pragma unroll
        for (int ks = 0; ks < 2; ks++) {
            int kb = ks * 32;   // byte offset of this k16 within a row

            uint32_t af1[2][2][4], af2[2][4];      // [hl][msub][4] / [msub][4]
            uint32_t bf1[2][4][2], bf2[4][2];      // [hl][nsub][2] / [nsub][2]
#pragma unroll
            for (int ms = 0; ms < 2; ms++) {
                uint32_t arow = (uint32_t)((mw + ms * 16 + mloc) * RSTRIDE + kb + akb);
                ldm_x4(af1[0][ms], sb + OFF_A1H + arow);
                ldm_x4(af1[1][ms], sb + OFF_A1L + arow);
                ldm_x4(af2[ms],    sb + OFF_A2H + arow);
            }
#pragma unroll
            for (int ns = 0; ns < 4; ns++) {
                uint32_t brow = (uint32_t)((nw + ns * 8 + nloc) * RSTRIDE + kb + bkb);
                ldm_x2(bf1[0][ns], sb + OFF_W1H + brow);
                ldm_x2(bf1[1][ns], sb + OFF_W1L + brow);
                ldm_x2(bf2[ns],    sb + OFF_W2H + brow);
            }
#pragma unroll
            for (int ms = 0; ms < 2; ms++) {
#pragma unroll
                for (int ns = 0; ns < 4; ns++) {
                    // path 1: hi*hi + hi*lo + lo*hi (compensated)
                    mma_bf16(acc1[ms][ns], af1[0][ms], bf1[0][ns]);
                    mma_bf16(acc1[ms][ns], af1[0][ms], bf1[1][ns]);
                    mma_bf16(acc1[ms][ns], af1[1][ms], bf1[0][ns]);
                    // path 2: hi*hi only (bi path ~100x smaller magnitude)
                    mma_bf16(acc2[ms][ns], af2[ms], bf2[ns]);
                }
            }
        }
        __syncthreads();
    }

    // ---- epilogue ----
    float2 b1v[4], b2v[4];
#pragma unroll
    for (int ns = 0; ns < 4; ns++) {
        int ng = j0 + nw + ns * 8 + 2 * (lane & 3);
        b1v[ns] = *reinterpret_cast<const float2*>(b1 + ng);
        b2v[ns] = *reinterpret_cast<const float2*>(b2 + ng);
    }
#pragma unroll
    for (int ms = 0; ms < 2; ms++) {
#pragma unroll
        for (int h = 0; h < 2; h++) {
            int gm = row0 + mw + ms * 16 + (lane >> 2) + h * 8;
            if (gm < N_NODES) {
#pragma unroll
                for (int ns = 0; ns < 4; ns++) {
                    int ng = j0 + nw + ns * 8 + 2 * (lane & 3);
                    float2 o;
                    o.x = lrelu(acc1[ms][ns][h * 2 + 0] + b1v[ns].x) +
                          lrelu(acc2[ms][ns][h * 2 + 0] + b2v[ns].x);
                    o.y = lrelu(acc1[ms][ns][h * 2 + 1] + b1v[ns].y) +
                          lrelu(acc2[ms][ns][h * 2 + 1] + b2v[ns].y);
                    *reinterpret_cast<float2*>(out + (size_t)gm * D + ng) = o;
                }
            }
        }
    }
}

// ===========================================================================
// Launch sequence (all graph-capturable, stream-ordered)
// ===========================================================================
extern "C" void kernel_launch(void* const* d_in, const int* in_sizes, int n_in,
                              void* d_out, int out_size) {
    const float* ego  = (const float*)d_in[0];
    const float* vals = (const float*)d_in[1];
    const float* W1   = (const float*)d_in[2];
    const float* b1   = (const float*)d_in[3];
    const float* W2   = (const float*)d_in[4];
    const float* b2   = (const float*)d_in[5];
    const int*   rows = (const int*)d_in[6];
    const int*   cols = (const int*)d_in[7];
    float*       out  = (float*)d_out;

    int E = in_sizes[1];
    int scan_blocks = (N_NODES + SCAN_B - 1) / SCAN_B;   // 98

    // independent prep
    ego_convert_kernel<<<(N_NODES * D / 8) / 256, 256>>>(ego);
    wsplit_kernel<<<(D * D + 255) / 256, 256>>>(W1, W2);

    // CSR build
    zero_cnt_kernel<<<(N_NODES + 255) / 256, 256>>>();
    hist_kernel<<<(E + 255) / 256, 256>>>(rows, E);
    scan1_kernel<<<scan_blocks, SCAN_B>>>();
    scan2_kernel<<<1, 128>>>(scan_blocks);
    scan3_kernel<<<scan_blocks, SCAN_B>>>(E);
    bucket_kernel<<<(E + 255) / 256, 256>>>(rows, cols, vals, E);

    // pull SpMM (bf16 gather) + A-operand split: one warp per row
    pull_spmm_kernel<<<(N_NODES * 32 + 255) / 256, 256>>>(ego);

    // HMMA dual GEMM + fused epilogue
    cudaFuncSetAttribute(gemm_mma_kernel,
                         cudaFuncAttributeMaxDynamicSharedMemorySize, SM_TOTAL);
    dim3 grid((N_NODES + 127) / 128, D / 64);   // 782 x 4
    gemm_mma_kernel<<<grid, 256, SM_TOTAL>>>(b1, b2, out);
}